// round 3
// baseline (speedup 1.0000x reference)
#include <cuda_runtime.h>
#include <cuda_fp8.h>
#include <cuda_fp16.h>
#include <cstdint>

// ===================== problem constants =====================
#define M_DIM 8192
#define K_DIM 4096
#define N_DIM 4096
#define KBC   (K_DIM / 128)              // 32 K-chunks of 128
#define NBC   (N_DIM / 128)              // 32 weight-block columns

// ===================== scratch (device globals, no malloc) =====================
__device__ __half g_qxh[(size_t)M_DIM * K_DIM];   // fp8-rounded activations, stored as half (exact)
__device__ float  g_sx[M_DIM * KBC];              // act scales [M, K/128]
__device__ __half g_qwh[(size_t)N_DIM * K_DIM];   // fp8-rounded weights, stored as half (exact)
__device__ float  g_sw[NBC * KBC];                // weight scales [N/128, K/128]

// ===================== helpers =====================
__device__ __forceinline__ uint32_t smem_u32(const void* p) {
    uint32_t a;
    asm("{ .reg .u64 t; cvta.to.shared.u64 t, %1; cvt.u32.u64 %0, t; }" : "=r"(a) : "l"(p));
    return a;
}

// fp8(e4m3, RN, satfinite) round-trip of (a*ratio, b*ratio), returned as packed half2 bits
__device__ __forceinline__ uint32_t q2h(float a, float b, float ratio) {
    float2 f = make_float2(a * ratio, b * ratio);
    __nv_fp8x2_storage_t p = __nv_cvt_float2_to_fp8x2(f, __NV_SATFINITE, __NV_E4M3);
    __half2_raw h = __nv_cvt_fp8x2_to_halfraw2(p, __NV_E4M3);
    uint32_t r;
    memcpy(&r, &h, 4);
    return r;
}

// ===================== quantization =====================
// One warp per (row, 128-col tile).
__global__ void quant_x_kernel(const float* __restrict__ x) {
    int gw   = (blockIdx.x * 256 + threadIdx.x) >> 5;
    int lane = threadIdx.x & 31;
    int row  = gw >> 5;             // KBC = 32 tiles per row
    int kb   = gw & 31;
    const float4 v = *(const float4*)(x + (size_t)row * K_DIM + kb * 128 + lane * 4);
    float amax = fmaxf(fmaxf(fabsf(v.x), fabsf(v.y)), fmaxf(fabsf(v.z), fabsf(v.w)));
    #pragma unroll
    for (int o = 16; o > 0; o >>= 1)
        amax = fmaxf(amax, __shfl_xor_sync(0xffffffffu, amax, o));
    float safe  = fmaxf(amax, 1e-4f);
    float ratio = 448.0f / safe;
    if (lane == 0) g_sx[row * KBC + kb] = safe / 448.0f;
    uint2 o2;
    o2.x = q2h(v.x, v.y, ratio);
    o2.y = q2h(v.z, v.w, ratio);
    *(uint2*)(g_qxh + (size_t)row * K_DIM + kb * 128 + lane * 4) = o2;
}

// One CTA per 128x128 weight block. grid = (KBC, NBC).
__global__ void quant_w_kernel(const float* __restrict__ w) {
    int kb = blockIdx.x, nb = blockIdx.y;
    int tid = threadIdx.x;
    const float* base = w + (size_t)nb * 128 * K_DIM + (size_t)kb * 128;
    float amax = 0.0f;
    #pragma unroll
    for (int i = 0; i < 16; i++) {
        int f = tid + i * 256;          // 0..4095 float4s
        int r = f >> 5, c = f & 31;
        float4 v = *(const float4*)(base + (size_t)r * K_DIM + c * 4);
        amax = fmaxf(amax, fmaxf(fmaxf(fabsf(v.x), fabsf(v.y)), fmaxf(fabsf(v.z), fabsf(v.w))));
    }
    #pragma unroll
    for (int o = 16; o > 0; o >>= 1)
        amax = fmaxf(amax, __shfl_xor_sync(0xffffffffu, amax, o));
    __shared__ float red[8];
    __shared__ float s_ratio;
    if ((tid & 31) == 0) red[tid >> 5] = amax;
    __syncthreads();
    if (tid == 0) {
        float a = red[0];
        #pragma unroll
        for (int i = 1; i < 8; i++) a = fmaxf(a, red[i]);
        float safe = fmaxf(a, 1e-6f);
        s_ratio = 448.0f / safe;
        g_sw[nb * KBC + kb] = safe / 448.0f;
    }
    __syncthreads();
    float ratio = s_ratio;
    __half* qbase = g_qwh + (size_t)nb * 128 * K_DIM + (size_t)kb * 128;
    #pragma unroll
    for (int i = 0; i < 16; i++) {
        int f = tid + i * 256;
        int r = f >> 5, c = f & 31;
        float4 v = *(const float4*)(base + (size_t)r * K_DIM + c * 4);
        uint2 o2;
        o2.x = q2h(v.x, v.y, ratio);
        o2.y = q2h(v.z, v.w, ratio);
        *(uint2*)(qbase + (size_t)r * K_DIM + c * 4) = o2;
    }
}

// ===================== GEMM =====================
// SMEM: per stage, A tile [128][128] half padded to 272B rows, B tile same.
static constexpr int ROW_BYTES   = 272;               // 256 data + 16 pad (conflict-free ldmatrix)
static constexpr int TILE_BYTES  = 128 * ROW_BYTES;   // 34816
static constexpr int STAGE_BYTES = 2 * TILE_BYTES;    // 69632 (A + B)
static constexpr int SMEM_TOTAL  = 2 * STAGE_BYTES;   // 139264 double-buffered

__device__ __forceinline__ void load_stage(uint32_t smem_base, int stage, int kb,
                                           int m0, int n0, int tid) {
    const __half* gA = g_qxh + (size_t)m0 * K_DIM + kb * 128;
    const __half* gB = g_qwh + (size_t)n0 * K_DIM + kb * 128;
    uint32_t sa = smem_base + stage * STAGE_BYTES;
    uint32_t sb = sa + TILE_BYTES;
    #pragma unroll
    for (int i = 0; i < 8; i++) {
        int idx = tid + i * 256;            // 0..2047
        int r = idx >> 4, c = idx & 15;     // 128 rows x 16 chunks of 16B
        uint32_t so = r * ROW_BYTES + c * 16;
        const void* ga = gA + (size_t)r * K_DIM + c * 8;
        asm volatile("cp.async.cg.shared.global [%0], [%1], 16;" :: "r"(sa + so), "l"(ga));
        const void* gb = gB + (size_t)r * K_DIM + c * 8;
        asm volatile("cp.async.cg.shared.global [%0], [%1], 16;" :: "r"(sb + so), "l"(gb));
    }
}

__global__ void __launch_bounds__(256, 1) gemm_fp8_kernel(float* __restrict__ out) {
    extern __shared__ char smem[];
    uint32_t smem_base = smem_u32(smem);
    int tid  = threadIdx.x;
    int lane = tid & 31;
    int wid  = tid >> 5;
    int wm = wid & 1;                 // 2 warps along M
    int wn = wid >> 1;                // 4 warps along N
    int nb = blockIdx.x;
    int n0 = nb * 128;
    int m0 = blockIdx.y * 128;

    float acc[4][4][4];
    #pragma unroll
    for (int i = 0; i < 4; i++)
        #pragma unroll
        for (int j = 0; j < 4; j++)
            #pragma unroll
            for (int q = 0; q < 4; q++) acc[i][j][q] = 0.0f;

    // per-lane ldmatrix base offsets (within a tile)
    // A (x4): lanes 0-15 -> rows, lanes 16-31 -> +16B col
    uint32_t a_off = (uint32_t)(wm * 64 + (lane & 15)) * ROW_BYTES + (lane >> 4) * 16;
    // B (x4): group g=lane>>3: rows (g>>1)*8 + lane&7, col (g&1)*16
    uint32_t b_off = (uint32_t)(wn * 32 + ((lane >> 4) << 3) + (lane & 7)) * ROW_BYTES
                   + (((lane >> 3) & 1) * 16);

    load_stage(smem_base, 0, 0, m0, n0, tid);
    asm volatile("cp.async.commit_group;" ::: "memory");

    #pragma unroll 1
    for (int kb = 0; kb < KBC; kb++) {
        if (kb < KBC - 1) {
            load_stage(smem_base, (kb + 1) & 1, kb + 1, m0, n0, tid);
            asm volatile("cp.async.commit_group;" ::: "memory");
            asm volatile("cp.async.wait_group 1;" ::: "memory");
        } else {
            asm volatile("cp.async.wait_group 0;" ::: "memory");
        }
        __syncthreads();

        // scales for this chunk
        float swv = g_sw[nb * KBC + kb];
        float cs0[4], cs1[4];
        #pragma unroll
        for (int i = 0; i < 4; i++) {
            int ra = m0 + wm * 64 + i * 16 + (lane >> 2);
            cs0[i] = g_sx[(size_t)ra * KBC + kb] * swv;
            cs1[i] = g_sx[(size_t)(ra + 8) * KBC + kb] * swv;
        }

        uint32_t sa = smem_base + (kb & 1) * STAGE_BYTES;
        uint32_t sb = sa + TILE_BYTES;

        float tmp[4][4][4];
        #pragma unroll
        for (int i = 0; i < 4; i++)
            #pragma unroll
            for (int j = 0; j < 4; j++)
                #pragma unroll
                for (int q = 0; q < 4; q++) tmp[i][j][q] = 0.0f;

        #pragma unroll
        for (int s = 0; s < 8; s++) {
            uint32_t af[4][4];
            #pragma unroll
            for (int i = 0; i < 4; i++) {
                uint32_t addr = sa + a_off + (uint32_t)i * 16 * ROW_BYTES + s * 32;
                asm volatile("ldmatrix.sync.aligned.m8n8.x4.shared.b16 {%0,%1,%2,%3}, [%4];"
                             : "=r"(af[i][0]), "=r"(af[i][1]), "=r"(af[i][2]), "=r"(af[i][3])
                             : "r"(addr));
            }
            uint32_t bf[8];   // ntiles 0..3, 2 regs each
            #pragma unroll
            for (int jp = 0; jp < 2; jp++) {
                uint32_t addr = sb + b_off + (uint32_t)jp * 16 * ROW_BYTES + s * 32;
                asm volatile("ldmatrix.sync.aligned.m8n8.x4.shared.b16 {%0,%1,%2,%3}, [%4];"
                             : "=r"(bf[jp * 4 + 0]), "=r"(bf[jp * 4 + 1]),
                               "=r"(bf[jp * 4 + 2]), "=r"(bf[jp * 4 + 3])
                             : "r"(addr));
            }
            #pragma unroll
            for (int i = 0; i < 4; i++)
                #pragma unroll
                for (int j = 0; j < 4; j++) {
                    asm volatile(
                        "mma.sync.aligned.m16n8k16.row.col.f32.f16.f16.f32 "
                        "{%0,%1,%2,%3}, {%4,%5,%6,%7}, {%8,%9}, {%0,%1,%2,%3};"
                        : "+f"(tmp[i][j][0]), "+f"(tmp[i][j][1]),
                          "+f"(tmp[i][j][2]), "+f"(tmp[i][j][3])
                        : "r"(af[i][0]), "r"(af[i][1]), "r"(af[i][2]), "r"(af[i][3]),
                          "r"(bf[j * 2]), "r"(bf[j * 2 + 1]));
                }
        }

        #pragma unroll
        for (int i = 0; i < 4; i++)
            #pragma unroll
            for (int j = 0; j < 4; j++) {
                acc[i][j][0] = fmaf(cs0[i], tmp[i][j][0], acc[i][j][0]);
                acc[i][j][1] = fmaf(cs0[i], tmp[i][j][1], acc[i][j][1]);
                acc[i][j][2] = fmaf(cs1[i], tmp[i][j][2], acc[i][j][2]);
                acc[i][j][3] = fmaf(cs1[i], tmp[i][j][3], acc[i][j][3]);
            }

        __syncthreads();
    }

    // epilogue
    #pragma unroll
    for (int i = 0; i < 4; i++) {
        int r0 = m0 + wm * 64 + i * 16 + (lane >> 2);
        #pragma unroll
        for (int j = 0; j < 4; j++) {
            int c = n0 + wn * 32 + j * 8 + 2 * (lane & 3);
            *(float2*)(out + (size_t)r0 * N_DIM + c)       = make_float2(acc[i][j][0], acc[i][j][1]);
            *(float2*)(out + (size_t)(r0 + 8) * N_DIM + c) = make_float2(acc[i][j][2], acc[i][j][3]);
        }
    }
}

// ===================== launch =====================
extern "C" void kernel_launch(void* const* d_in, const int* in_sizes, int n_in,
                              void* d_out, int out_size) {
    const float* x = (const float*)d_in[0];
    const float* w = (const float*)d_in[1];
    float* out = (float*)d_out;

    static bool attr_done = false;
    if (!attr_done) {
        cudaFuncSetAttribute(gemm_fp8_kernel,
                             cudaFuncAttributeMaxDynamicSharedMemorySize, SMEM_TOTAL);
        attr_done = true;
    }

    quant_x_kernel<<<(M_DIM * KBC) / 8, 256>>>(x);
    quant_w_kernel<<<dim3(KBC, NBC), 256>>>(w);
    gemm_fp8_kernel<<<dim3(N_DIM / 128, M_DIM / 128), 256, SMEM_TOTAL>>>(out);
}

// round 4
// speedup vs baseline: 1.1242x; 1.1242x over previous
#include <cuda_runtime.h>
#include <cuda_fp8.h>
#include <cuda_fp16.h>
#include <cstdint>
#include <cstring>

// ===================== problem constants =====================
#define M_DIM 8192
#define K_DIM 4096
#define N_DIM 4096
#define KBC   (K_DIM / 128)              // 32 K-chunks of 128
#define NBC   (N_DIM / 128)              // 32 weight-block columns

// ===================== scratch (device globals, no malloc) =====================
__device__ uint8_t g_qx[(size_t)M_DIM * K_DIM];   // fp8 e4m3 activations
__device__ float   g_sx[M_DIM * KBC];             // act scales [M, K/128]
__device__ uint8_t g_qw[(size_t)N_DIM * K_DIM];   // fp8 e4m3 weights
__device__ float   g_sw[NBC * KBC];               // weight scales [N/128, K/128]

// ===================== helpers =====================
__device__ __forceinline__ uint32_t smem_u32(const void* p) {
    uint32_t a;
    asm("{ .reg .u64 t; cvta.to.shared.u64 t, %1; cvt.u32.u64 %0, t; }" : "=r"(a) : "l"(p));
    return a;
}

// fp8(e4m3, RN, satfinite) of 4 scaled floats, packed into u32
__device__ __forceinline__ uint32_t q4(float4 v, float ratio) {
    __nv_fp8x2_storage_t lo =
        __nv_cvt_float2_to_fp8x2(make_float2(v.x * ratio, v.y * ratio), __NV_SATFINITE, __NV_E4M3);
    __nv_fp8x2_storage_t hi =
        __nv_cvt_float2_to_fp8x2(make_float2(v.z * ratio, v.w * ratio), __NV_SATFINITE, __NV_E4M3);
    return (uint32_t)lo | ((uint32_t)hi << 16);
}

// ===================== quantization =====================
// One warp per (row, 128-col tile).
__global__ void quant_x_kernel(const float* __restrict__ x) {
    int gw   = (blockIdx.x * 256 + threadIdx.x) >> 5;
    int lane = threadIdx.x & 31;
    int row  = gw >> 5;             // KBC = 32 tiles per row
    int kb   = gw & 31;
    const float4 v = *(const float4*)(x + (size_t)row * K_DIM + kb * 128 + lane * 4);
    float amax = fmaxf(fmaxf(fabsf(v.x), fabsf(v.y)), fmaxf(fabsf(v.z), fabsf(v.w)));
    #pragma unroll
    for (int o = 16; o > 0; o >>= 1)
        amax = fmaxf(amax, __shfl_xor_sync(0xffffffffu, amax, o));
    float safe  = fmaxf(amax, 1e-4f);
    float ratio = 448.0f / safe;
    if (lane == 0) g_sx[row * KBC + kb] = safe / 448.0f;
    *(uint32_t*)(g_qx + (size_t)row * K_DIM + kb * 128 + lane * 4) = q4(v, ratio);
}

// One CTA per 128x128 weight block. grid = (KBC, NBC).
__global__ void quant_w_kernel(const float* __restrict__ w) {
    int kb = blockIdx.x, nb = blockIdx.y;
    int tid = threadIdx.x;
    const float* base = w + (size_t)nb * 128 * K_DIM + (size_t)kb * 128;
    float amax = 0.0f;
    #pragma unroll
    for (int i = 0; i < 16; i++) {
        int f = tid + i * 256;          // 0..4095 float4s
        int r = f >> 5, c = f & 31;
        float4 v = *(const float4*)(base + (size_t)r * K_DIM + c * 4);
        amax = fmaxf(amax, fmaxf(fmaxf(fabsf(v.x), fabsf(v.y)), fmaxf(fabsf(v.z), fabsf(v.w))));
    }
    #pragma unroll
    for (int o = 16; o > 0; o >>= 1)
        amax = fmaxf(amax, __shfl_xor_sync(0xffffffffu, amax, o));
    __shared__ float red[8];
    __shared__ float s_ratio;
    if ((tid & 31) == 0) red[tid >> 5] = amax;
    __syncthreads();
    if (tid == 0) {
        float a = red[0];
        #pragma unroll
        for (int i = 1; i < 8; i++) a = fmaxf(a, red[i]);
        float safe = fmaxf(a, 1e-6f);
        s_ratio = 448.0f / safe;
        g_sw[nb * KBC + kb] = safe / 448.0f;
    }
    __syncthreads();
    float ratio = s_ratio;
    uint8_t* qbase = g_qw + (size_t)nb * 128 * K_DIM + (size_t)kb * 128;
    #pragma unroll
    for (int i = 0; i < 16; i++) {
        int f = tid + i * 256;
        int r = f >> 5, c = f & 31;
        float4 v = *(const float4*)(base + (size_t)r * K_DIM + c * 4);
        *(uint32_t*)(qbase + (size_t)r * K_DIM + c * 4) = q4(v, ratio);
    }
}

// ===================== GEMM =====================
// fp8 tiles: 128 rows x 128 bytes, padded to 144B rows (conflict-free ldmatrix).
static constexpr int ROW_BYTES   = 144;               // 128 data + 16 pad
static constexpr int TILE_BYTES  = 128 * ROW_BYTES;   // 18432
static constexpr int STAGE_BYTES = 2 * TILE_BYTES;    // 36864 (A + B)
static constexpr int NSTAGE      = 4;
static constexpr int SMEM_TOTAL  = NSTAGE * STAGE_BYTES;  // 147456

__device__ __forceinline__ void load_stage(uint32_t smem_base, int stage, int kb,
                                           int m0, int n0, int tid) {
    const uint8_t* gA = g_qx + (size_t)m0 * K_DIM + kb * 128;
    const uint8_t* gB = g_qw + (size_t)n0 * K_DIM + kb * 128;
    uint32_t sa = smem_base + stage * STAGE_BYTES;
    uint32_t sb = sa + TILE_BYTES;
    #pragma unroll
    for (int i = 0; i < 4; i++) {
        int idx = tid + i * 256;            // 0..1023
        int r = idx >> 3, c = idx & 7;      // 128 rows x 8 chunks of 16B
        uint32_t so = r * ROW_BYTES + c * 16;
        const void* ga = gA + (size_t)r * K_DIM + c * 16;
        asm volatile("cp.async.cg.shared.global [%0], [%1], 16;" :: "r"(sa + so), "l"(ga));
        const void* gb = gB + (size_t)r * K_DIM + c * 16;
        asm volatile("cp.async.cg.shared.global [%0], [%1], 16;" :: "r"(sb + so), "l"(gb));
    }
}

__global__ void __launch_bounds__(256, 1) gemm_fp8_kernel(float* __restrict__ out) {
    extern __shared__ char smem[];
    uint32_t smem_base = smem_u32(smem);
    int tid  = threadIdx.x;
    int lane = tid & 31;
    int wid  = tid >> 5;
    int wm = wid & 1;                 // 2 warps along M  (64 rows each)
    int wn = wid >> 1;                // 4 warps along N  (32 cols each)
    int nb = blockIdx.x;
    int n0 = nb * 128;
    int m0 = blockIdx.y * 128;

    float acc[4][4][4];
    #pragma unroll
    for (int i = 0; i < 4; i++)
        #pragma unroll
        for (int j = 0; j < 4; j++)
            #pragma unroll
            for (int q = 0; q < 4; q++) acc[i][j][q] = 0.0f;

    // ldmatrix lane offsets within a tile (b16 view of fp8 bytes):
    // A m16k32 tile: 16 rows x 32 bytes = 4x (8 rows x 16B) submatrices
    uint32_t a_off = (uint32_t)(wm * 64 + (lane & 15)) * ROW_BYTES + (lane >> 4) * 16;
    // B n8k32 pairs: rows = n, 16B k-halves
    uint32_t b_off = (uint32_t)(wn * 32 + ((lane >> 4) << 3) + (lane & 7)) * ROW_BYTES
                   + (((lane >> 3) & 1) * 16);

    // prologue: fill 3 stages
    load_stage(smem_base, 0, 0, m0, n0, tid);
    asm volatile("cp.async.commit_group;" ::: "memory");
    load_stage(smem_base, 1, 1, m0, n0, tid);
    asm volatile("cp.async.commit_group;" ::: "memory");
    load_stage(smem_base, 2, 2, m0, n0, tid);
    asm volatile("cp.async.commit_group;" ::: "memory");

    #pragma unroll 1
    for (int kb = 0; kb < KBC; kb++) {
        asm volatile("cp.async.wait_group 2;" ::: "memory");
        __syncthreads();

        // issue load for kb+3 into the stage freed by iteration kb-1
        if (kb + 3 < KBC)
            load_stage(smem_base, (kb + 3) & (NSTAGE - 1), kb + 3, m0, n0, tid);
        asm volatile("cp.async.commit_group;" ::: "memory");

        // scales for this chunk
        float swv = g_sw[nb * KBC + kb];
        float cs0[4], cs1[4];
        #pragma unroll
        for (int i = 0; i < 4; i++) {
            int ra = m0 + wm * 64 + i * 16 + (lane >> 2);
            cs0[i] = g_sx[(size_t)ra * KBC + kb] * swv;
            cs1[i] = g_sx[(size_t)(ra + 8) * KBC + kb] * swv;
        }

        uint32_t sa = smem_base + (kb & (NSTAGE - 1)) * STAGE_BYTES;
        uint32_t sb = sa + TILE_BYTES;

        float tmp[4][4][4];
        #pragma unroll
        for (int i = 0; i < 4; i++)
            #pragma unroll
            for (int j = 0; j < 4; j++)
                #pragma unroll
                for (int q = 0; q < 4; q++) tmp[i][j][q] = 0.0f;

        #pragma unroll
        for (int s = 0; s < 4; s++) {       // 4 k32 steps of 32 bytes
            uint32_t af[4][4];
            #pragma unroll
            for (int i = 0; i < 4; i++) {
                uint32_t addr = sa + a_off + (uint32_t)i * 16 * ROW_BYTES + s * 32;
                asm volatile("ldmatrix.sync.aligned.m8n8.x4.shared.b16 {%0,%1,%2,%3}, [%4];"
                             : "=r"(af[i][0]), "=r"(af[i][1]), "=r"(af[i][2]), "=r"(af[i][3])
                             : "r"(addr));
            }
            uint32_t bf[8];                 // 4 n-tiles x 2 regs
            #pragma unroll
            for (int jp = 0; jp < 2; jp++) {
                uint32_t addr = sb + b_off + (uint32_t)jp * 16 * ROW_BYTES + s * 32;
                asm volatile("ldmatrix.sync.aligned.m8n8.x4.shared.b16 {%0,%1,%2,%3}, [%4];"
                             : "=r"(bf[jp * 4 + 0]), "=r"(bf[jp * 4 + 1]),
                               "=r"(bf[jp * 4 + 2]), "=r"(bf[jp * 4 + 3])
                             : "r"(addr));
            }
            #pragma unroll
            for (int i = 0; i < 4; i++)
                #pragma unroll
                for (int j = 0; j < 4; j++) {
                    asm volatile(
                        "mma.sync.aligned.m16n8k32.row.col.f32.e4m3.e4m3.f32 "
                        "{%0,%1,%2,%3}, {%4,%5,%6,%7}, {%8,%9}, {%0,%1,%2,%3};"
                        : "+f"(tmp[i][j][0]), "+f"(tmp[i][j][1]),
                          "+f"(tmp[i][j][2]), "+f"(tmp[i][j][3])
                        : "r"(af[i][0]), "r"(af[i][1]), "r"(af[i][2]), "r"(af[i][3]),
                          "r"(bf[j * 2]), "r"(bf[j * 2 + 1]));
                }
        }

        #pragma unroll
        for (int i = 0; i < 4; i++)
            #pragma unroll
            for (int j = 0; j < 4; j++) {
                acc[i][j][0] = fmaf(cs0[i], tmp[i][j][0], acc[i][j][0]);
                acc[i][j][1] = fmaf(cs0[i], tmp[i][j][1], acc[i][j][1]);
                acc[i][j][2] = fmaf(cs1[i], tmp[i][j][2], acc[i][j][2]);
                acc[i][j][3] = fmaf(cs1[i], tmp[i][j][3], acc[i][j][3]);
            }
    }

    // epilogue
    #pragma unroll
    for (int i = 0; i < 4; i++) {
        int r0 = m0 + wm * 64 + i * 16 + (lane >> 2);
        #pragma unroll
        for (int j = 0; j < 4; j++) {
            int c = n0 + wn * 32 + j * 8 + 2 * (lane & 3);
            *(float2*)(out + (size_t)r0 * N_DIM + c)       = make_float2(acc[i][j][0], acc[i][j][1]);
            *(float2*)(out + (size_t)(r0 + 8) * N_DIM + c) = make_float2(acc[i][j][2], acc[i][j][3]);
        }
    }
}

// ===================== launch =====================
extern "C" void kernel_launch(void* const* d_in, const int* in_sizes, int n_in,
                              void* d_out, int out_size) {
    const float* x = (const float*)d_in[0];
    const float* w = (const float*)d_in[1];
    float* out = (float*)d_out;

    cudaFuncSetAttribute(gemm_fp8_kernel,
                         cudaFuncAttributeMaxDynamicSharedMemorySize, SMEM_TOTAL);

    quant_x_kernel<<<(M_DIM * KBC) / 8, 256>>>(x);
    quant_w_kernel<<<dim3(KBC, NBC), 256>>>(w);
    gemm_fp8_kernel<<<dim3(N_DIM / 128, M_DIM / 128), 256, SMEM_TOTAL>>>(out);
}

// round 5
// speedup vs baseline: 1.2130x; 1.0790x over previous
#include <cuda_runtime.h>
#include <cuda_fp8.h>
#include <cuda_fp16.h>
#include <cstdint>
#include <cstring>

// ===================== problem constants =====================
#define M_DIM 8192
#define K_DIM 4096
#define N_DIM 4096
#define KBC   (K_DIM / 128)              // 32 K-chunks of 128
#define NBC   (N_DIM / 128)              // 32 weight-block columns

// ===================== scratch (device globals, no malloc) =====================
__device__ uint8_t g_qx[(size_t)M_DIM * K_DIM];   // fp8 e4m3 activations
__device__ float   g_sx[M_DIM * KBC];             // act scales [M, K/128]
__device__ uint8_t g_qw[(size_t)N_DIM * K_DIM];   // fp8 e4m3 weights
__device__ float   g_sw[NBC * KBC];               // weight scales [N/128, K/128]

// ===================== helpers =====================
__device__ __forceinline__ uint32_t smem_u32(const void* p) {
    uint32_t a;
    asm("{ .reg .u64 t; cvta.to.shared.u64 t, %1; cvt.u32.u64 %0, t; }" : "=r"(a) : "l"(p));
    return a;
}

// fp8(e4m3, RN, satfinite) of 4 scaled floats, packed into u32
__device__ __forceinline__ uint32_t q4(float4 v, float ratio) {
    __nv_fp8x2_storage_t lo =
        __nv_cvt_float2_to_fp8x2(make_float2(v.x * ratio, v.y * ratio), __NV_SATFINITE, __NV_E4M3);
    __nv_fp8x2_storage_t hi =
        __nv_cvt_float2_to_fp8x2(make_float2(v.z * ratio, v.w * ratio), __NV_SATFINITE, __NV_E4M3);
    return (uint32_t)lo | ((uint32_t)hi << 16);
}

// ===================== quantization =====================
// One warp per (row, 128-col tile).
__global__ void quant_x_kernel(const float* __restrict__ x) {
    int gw   = (blockIdx.x * 256 + threadIdx.x) >> 5;
    int lane = threadIdx.x & 31;
    int row  = gw >> 5;             // KBC = 32 tiles per row
    int kb   = gw & 31;
    const float4 v = *(const float4*)(x + (size_t)row * K_DIM + kb * 128 + lane * 4);
    float amax = fmaxf(fmaxf(fabsf(v.x), fabsf(v.y)), fmaxf(fabsf(v.z), fabsf(v.w)));
    #pragma unroll
    for (int o = 16; o > 0; o >>= 1)
        amax = fmaxf(amax, __shfl_xor_sync(0xffffffffu, amax, o));
    float safe  = fmaxf(amax, 1e-4f);
    float ratio = 448.0f / safe;
    if (lane == 0) g_sx[row * KBC + kb] = safe / 448.0f;
    *(uint32_t*)(g_qx + (size_t)row * K_DIM + kb * 128 + lane * 4) = q4(v, ratio);
}

// One CTA per 128x128 weight block. grid = (KBC, NBC).
__global__ void quant_w_kernel(const float* __restrict__ w) {
    int kb = blockIdx.x, nb = blockIdx.y;
    int tid = threadIdx.x;
    const float* base = w + (size_t)nb * 128 * K_DIM + (size_t)kb * 128;
    float amax = 0.0f;
    #pragma unroll
    for (int i = 0; i < 16; i++) {
        int f = tid + i * 256;          // 0..4095 float4s
        int r = f >> 5, c = f & 31;
        float4 v = *(const float4*)(base + (size_t)r * K_DIM + c * 4);
        amax = fmaxf(amax, fmaxf(fmaxf(fabsf(v.x), fabsf(v.y)), fmaxf(fabsf(v.z), fabsf(v.w))));
    }
    #pragma unroll
    for (int o = 16; o > 0; o >>= 1)
        amax = fmaxf(amax, __shfl_xor_sync(0xffffffffu, amax, o));
    __shared__ float red[8];
    __shared__ float s_ratio;
    if ((tid & 31) == 0) red[tid >> 5] = amax;
    __syncthreads();
    if (tid == 0) {
        float a = red[0];
        #pragma unroll
        for (int i = 1; i < 8; i++) a = fmaxf(a, red[i]);
        float safe = fmaxf(a, 1e-6f);
        s_ratio = 448.0f / safe;
        g_sw[nb * KBC + kb] = safe / 448.0f;
    }
    __syncthreads();
    float ratio = s_ratio;
    uint8_t* qbase = g_qw + (size_t)nb * 128 * K_DIM + (size_t)kb * 128;
    #pragma unroll
    for (int i = 0; i < 16; i++) {
        int f = tid + i * 256;
        int r = f >> 5, c = f & 31;
        float4 v = *(const float4*)(base + (size_t)r * K_DIM + c * 4);
        *(uint32_t*)(qbase + (size_t)r * K_DIM + c * 4) = q4(v, ratio);
    }
}

// ===================== GEMM =====================
// fp8 tiles: 128 rows x 128 bytes, padded to 144B rows (conflict-free ldmatrix).
// SMEM layout: [0,16384) act-scale block, [16384,16512) weight scales,
//              [16512, +4*36864) pipeline stages.
static constexpr int ROW_BYTES   = 144;               // 128 data + 16 pad
static constexpr int TILE_BYTES  = 128 * ROW_BYTES;   // 18432
static constexpr int STAGE_BYTES = 2 * TILE_BYTES;    // 36864 (A + B)
static constexpr int NSTAGE      = 4;
static constexpr int SCALE_BYTES = 128 * KBC * 4 + 128;   // 16512
static constexpr int SMEM_TOTAL  = SCALE_BYTES + NSTAGE * STAGE_BYTES;  // 163968

__device__ __forceinline__ void load_stage(uint32_t stage_base, int stage, int kb,
                                           int m0, int n0, int tid) {
    const uint8_t* gA = g_qx + (size_t)m0 * K_DIM + kb * 128;
    const uint8_t* gB = g_qw + (size_t)n0 * K_DIM + kb * 128;
    uint32_t sa = stage_base + stage * STAGE_BYTES;
    uint32_t sb = sa + TILE_BYTES;
    #pragma unroll
    for (int i = 0; i < 2; i++) {
        int idx = tid + i * 512;            // 0..1023
        int r = idx >> 3, c = idx & 7;      // 128 rows x 8 chunks of 16B
        uint32_t so = r * ROW_BYTES + c * 16;
        const void* ga = gA + (size_t)r * K_DIM + c * 16;
        asm volatile("cp.async.cg.shared.global [%0], [%1], 16;" :: "r"(sa + so), "l"(ga));
        const void* gb = gB + (size_t)r * K_DIM + c * 16;
        asm volatile("cp.async.cg.shared.global [%0], [%1], 16;" :: "r"(sb + so), "l"(gb));
    }
}

__global__ void __launch_bounds__(512, 1) gemm_fp8_kernel(float* __restrict__ out) {
    extern __shared__ char smem[];
    uint32_t smem_base  = smem_u32(smem);
    uint32_t stage_base = smem_base + SCALE_BYTES;
    int tid  = threadIdx.x;
    int lane = tid & 31;
    int wid  = tid >> 5;
    int wm = wid & 3;                 // 4 warps along M  (32 rows each)
    int wn = wid >> 2;                // 4 warps along N  (32 cols each)
    int nb = blockIdx.x;
    int n0 = nb * 128;
    int m0 = blockIdx.y * 128;

    // prologue: start pipeline before anything else
    load_stage(stage_base, 0, 0, m0, n0, tid);
    asm volatile("cp.async.commit_group;" ::: "memory");
    load_stage(stage_base, 1, 1, m0, n0, tid);
    asm volatile("cp.async.commit_group;" ::: "memory");
    load_stage(stage_base, 2, 2, m0, n0, tid);
    asm volatile("cp.async.commit_group;" ::: "memory");

    // copy this CTA's scales into SMEM (contiguous 128*KBC floats) + 32 sw floats
    {
        const float4* src = (const float4*)(g_sx + (size_t)m0 * KBC);
        float4* dst = (float4*)smem;
        dst[tid]       = src[tid];
        dst[tid + 512] = src[tid + 512];
        if (tid < 8)
            ((float4*)(smem + 128 * KBC * 4))[tid] = ((const float4*)(g_sw + nb * KBC))[tid];
    }
    __syncthreads();

    float acc[2][4][4];
    #pragma unroll
    for (int i = 0; i < 2; i++)
        #pragma unroll
        for (int j = 0; j < 4; j++)
            #pragma unroll
            for (int q = 0; q < 4; q++) acc[i][j][q] = 0.0f;

    // ldmatrix lane offsets within a tile (b16 view of fp8 bytes)
    uint32_t a_off = (uint32_t)(wm * 32 + (lane & 15)) * ROW_BYTES + (lane >> 4) * 16;
    uint32_t b_off = (uint32_t)(wn * 32 + ((lane >> 4) << 3) + (lane & 7)) * ROW_BYTES
                   + (((lane >> 3) & 1) * 16);

    // in-SMEM scale addresses for this thread's accumulator rows
    int ra0 = wm * 32 + (lane >> 2);       // rows ra0, ra0+8, ra0+16, ra0+24
    const float* s_sx = (const float*)smem;
    const float* s_sw = (const float*)(smem + 128 * KBC * 4);

    #pragma unroll 1
    for (int kb = 0; kb < KBC; kb++) {
        asm volatile("cp.async.wait_group 2;" ::: "memory");
        __syncthreads();

        if (kb + 3 < KBC)
            load_stage(stage_base, (kb + 3) & (NSTAGE - 1), kb + 3, m0, n0, tid);
        asm volatile("cp.async.commit_group;" ::: "memory");

        float swv = s_sw[kb];
        float cs0[2], cs1[2];
        #pragma unroll
        for (int i = 0; i < 2; i++) {
            cs0[i] = s_sx[(ra0 + i * 16) * KBC + kb] * swv;
            cs1[i] = s_sx[(ra0 + i * 16 + 8) * KBC + kb] * swv;
        }

        uint32_t sa = stage_base + (kb & (NSTAGE - 1)) * STAGE_BYTES;
        uint32_t sb = sa + TILE_BYTES;

        float tmp[2][4][4];
        #pragma unroll
        for (int i = 0; i < 2; i++)
            #pragma unroll
            for (int j = 0; j < 4; j++)
                #pragma unroll
                for (int q = 0; q < 4; q++) tmp[i][j][q] = 0.0f;

        #pragma unroll
        for (int s = 0; s < 4; s++) {       // 4 k32 steps of 32 bytes
            uint32_t af[2][4];
            #pragma unroll
            for (int i = 0; i < 2; i++) {
                uint32_t addr = sa + a_off + (uint32_t)i * 16 * ROW_BYTES + s * 32;
                asm volatile("ldmatrix.sync.aligned.m8n8.x4.shared.b16 {%0,%1,%2,%3}, [%4];"
                             : "=r"(af[i][0]), "=r"(af[i][1]), "=r"(af[i][2]), "=r"(af[i][3])
                             : "r"(addr));
            }
            uint32_t bf[8];                 // 4 n-tiles x 2 regs
            #pragma unroll
            for (int jp = 0; jp < 2; jp++) {
                uint32_t addr = sb + b_off + (uint32_t)jp * 16 * ROW_BYTES + s * 32;
                asm volatile("ldmatrix.sync.aligned.m8n8.x4.shared.b16 {%0,%1,%2,%3}, [%4];"
                             : "=r"(bf[jp * 4 + 0]), "=r"(bf[jp * 4 + 1]),
                               "=r"(bf[jp * 4 + 2]), "=r"(bf[jp * 4 + 3])
                             : "r"(addr));
            }
            #pragma unroll
            for (int i = 0; i < 2; i++)
                #pragma unroll
                for (int j = 0; j < 4; j++) {
                    asm volatile(
                        "mma.sync.aligned.m16n8k32.row.col.f32.e4m3.e4m3.f32 "
                        "{%0,%1,%2,%3}, {%4,%5,%6,%7}, {%8,%9}, {%0,%1,%2,%3};"
                        : "+f"(tmp[i][j][0]), "+f"(tmp[i][j][1]),
                          "+f"(tmp[i][j][2]), "+f"(tmp[i][j][3])
                        : "r"(af[i][0]), "r"(af[i][1]), "r"(af[i][2]), "r"(af[i][3]),
                          "r"(bf[j * 2]), "r"(bf[j * 2 + 1]));
                }
        }

        #pragma unroll
        for (int i = 0; i < 2; i++)
            #pragma unroll
            for (int j = 0; j < 4; j++) {
                acc[i][j][0] = fmaf(cs0[i], tmp[i][j][0], acc[i][j][0]);
                acc[i][j][1] = fmaf(cs0[i], tmp[i][j][1], acc[i][j][1]);
                acc[i][j][2] = fmaf(cs1[i], tmp[i][j][2], acc[i][j][2]);
                acc[i][j][3] = fmaf(cs1[i], tmp[i][j][3], acc[i][j][3]);
            }
    }

    // epilogue
    #pragma unroll
    for (int i = 0; i < 2; i++) {
        int r0 = m0 + wm * 32 + i * 16 + (lane >> 2);
        #pragma unroll
        for (int j = 0; j < 4; j++) {
            int c = n0 + wn * 32 + j * 8 + 2 * (lane & 3);
            *(float2*)(out + (size_t)r0 * N_DIM + c)       = make_float2(acc[i][j][0], acc[i][j][1]);
            *(float2*)(out + (size_t)(r0 + 8) * N_DIM + c) = make_float2(acc[i][j][2], acc[i][j][3]);
        }
    }
}

// ===================== launch =====================
extern "C" void kernel_launch(void* const* d_in, const int* in_sizes, int n_in,
                              void* d_out, int out_size) {
    const float* x = (const float*)d_in[0];
    const float* w = (const float*)d_in[1];
    float* out = (float*)d_out;

    cudaFuncSetAttribute(gemm_fp8_kernel,
                         cudaFuncAttributeMaxDynamicSharedMemorySize, SMEM_TOTAL);

    quant_x_kernel<<<(M_DIM * KBC) / 8, 256>>>(x);
    quant_w_kernel<<<dim3(KBC, NBC), 256>>>(w);
    gemm_fp8_kernel<<<dim3(N_DIM / 128, M_DIM / 128), 512, SMEM_TOTAL>>>(out);
}